// round 9
// baseline (speedup 1.0000x reference)
#include <cuda_runtime.h>
#include <cuda_fp16.h>
#include <cstdint>

// ---------------------------------------------------------------------------
// BayesKerasDense TT-dense: y = relu(x @ M + b)
// Stage 1: materialize TT-matrix M (fp16, transposed) + x -> fp16.
// Stage 2: mma.sync fp16 GEMM with **fp16 accumulation** (promote to fp32
//          every K=32) — testing whether the sm_103 HMMA pipe runs f16-accum
//          at 2x the f32-accum rate (fp32-accum path measured at its ceiling,
//          ~16 cyc/SMSP per mma -> ~480us floor).
// GEMM: CTA 128x256, BK=64, 4-stage cp.async ring, 8 warps x (64x64),
//       SW128 swizzle with XOR k-slice offsets.
// ---------------------------------------------------------------------------

#define NF 4096

__device__ float  g_T2[64 * 64 * 16];          // 256 KB
__device__ float  g_T3[512 * 512 * 16];        // 16.8 MB
__device__ __half g_Mt[(size_t)NF * NF];       // 32 MB, [n][k]
__device__ __half g_Xh[(size_t)NF * NF];       // 32 MB, [m][k]

// ---------------- stage 1: prep kernels ------------------------------------

// fused: blocks [0,256) build T2; blocks [256, 16640) convert x -> fp16
__global__ void k_prep0(const float* __restrict__ c0, const float* __restrict__ c1,
                        const float4* __restrict__ x4) {
    if (blockIdx.x < 256) {
        int idx = blockIdx.x * 256 + threadIdx.x;    // 65536 T2 elements
        int r2 = idx & 15;
        int q2 = (idx >> 4) & 63;
        int p2 = idx >> 10;
        int a0 = p2 >> 3, a1 = p2 & 7;
        int b0 = q2 >> 3, b1 = q2 & 7;
        float s = 0.f;
#pragma unroll
        for (int r1 = 0; r1 < 16; ++r1)
            s += c0[(a0 * 8 + b0) * 16 + r1] * c1[((r1 * 8 + a1) * 8 + b1) * 16 + r2];
        g_T2[idx] = s;
    } else {
        int idx = (blockIdx.x - 256) * 256 + threadIdx.x;  // 4194304 float4 chunks
        float4 v = x4[idx];
        __half2* o = (__half2*)g_Xh;
        o[idx * 2 + 0] = __floats2half2_rn(v.x, v.y);
        o[idx * 2 + 1] = __floats2half2_rn(v.z, v.w);
    }
}

__global__ void k_build_T3(const float* __restrict__ c2) {
    int idx = blockIdx.x * blockDim.x + threadIdx.x;
    if (idx >= 512 * 512 * 16) return;
    int r3 = idx & 15;
    int q3 = (idx >> 4) & 511;
    int p3 = idx >> 13;
    int p2 = p3 >> 3, a2 = p3 & 7;
    int q2 = q3 >> 3, b2 = q3 & 7;
    const float* t2 = &g_T2[((p2 << 6) + q2) << 4];
    float s = 0.f;
#pragma unroll
    for (int r2 = 0; r2 < 16; ++r2)
        s += t2[r2] * c2[((r2 * 8 + a2) * 8 + b2) * 16 + r3];
    g_T3[idx] = s;
}

__global__ void k_build_M(const float* __restrict__ c3) {
    int idx = blockIdx.x * blockDim.x + threadIdx.x;
    if (idx >= NF * NF) return;
    int a = idx & (NF - 1);
    int b = idx >> 12;
    int a3 = a & 7, p3 = a >> 3;
    int b3 = b & 7, q3 = b >> 3;
    const float* t3 = &g_T3[(((size_t)p3 << 9) + q3) << 4];
    float s = 0.f;
#pragma unroll
    for (int r3 = 0; r3 < 16; ++r3)
        s += t3[r3] * c3[(r3 * 8 + a3) * 8 + b3];
    g_Mt[(size_t)b * NF + a] = __float2half(s);
}

__global__ void k_nop() {}   // keeps ncu's fixed capture slot aligned on k_gemm

// ---------------- stage 2: fp16 HMMA GEMM ----------------------------------

#define BM 128
#define BN 256
#define BK 64
#define KT (NF / BK)                 // 64
#define A_BYTES (BM * 128)           // 16 KB
#define B_BYTES (BN * 128)           // 32 KB
#define STAGE_BYTES (A_BYTES + B_BYTES)   // 48 KB
#define STAGES 4
#define SMEM_TOTAL (STAGES * STAGE_BYTES) // 192 KB

__device__ __forceinline__ uint32_t sw128(uint32_t off) {
    return off ^ ((off >> 3) & 0x70);
}
__device__ __forceinline__ void cp_async16(uint32_t smem, const void* gmem) {
    asm volatile("cp.async.cg.shared.global [%0], [%1], 16;\n" :: "r"(smem), "l"(gmem));
}
__device__ __forceinline__ void cp_commit() {
    asm volatile("cp.async.commit_group;\n" ::: "memory");
}
__device__ __forceinline__ void ldmatrix_x4(uint32_t* r, uint32_t s) {
    asm volatile("ldmatrix.sync.aligned.m8n8.x4.shared.b16 {%0,%1,%2,%3}, [%4];\n"
                 : "=r"(r[0]), "=r"(r[1]), "=r"(r[2]), "=r"(r[3]) : "r"(s));
}
// f16-accum mma, C = 0 (z must be a zero register)
__device__ __forceinline__ void mma_h_z(uint32_t* d, const uint32_t* a,
                                        const uint32_t* b, uint32_t z) {
    asm volatile("mma.sync.aligned.m16n8k16.row.col.f16.f16.f16.f16 "
                 "{%0,%1}, {%2,%3,%4,%5}, {%6,%7}, {%8,%8};\n"
                 : "=r"(d[0]), "=r"(d[1])
                 : "r"(a[0]), "r"(a[1]), "r"(a[2]), "r"(a[3]),
                   "r"(b[0]), "r"(b[1]), "r"(z));
}
// f16-accum mma, C = D
__device__ __forceinline__ void mma_h(uint32_t* d, const uint32_t* a,
                                      const uint32_t* b) {
    asm volatile("mma.sync.aligned.m16n8k16.row.col.f16.f16.f16.f16 "
                 "{%0,%1}, {%2,%3,%4,%5}, {%6,%7}, {%0,%1};\n"
                 : "+r"(d[0]), "+r"(d[1])
                 : "r"(a[0]), "r"(a[1]), "r"(a[2]), "r"(a[3]),
                   "r"(b[0]), "r"(b[1]));
}

__global__ __launch_bounds__(256, 1) void k_gemm(const float* __restrict__ bias,
                                                 float* __restrict__ out) {
    extern __shared__ char smem[];
    uint32_t sb;
    asm("{ .reg .u64 t; cvta.to.shared.u64 t, %1; cvt.u32.u64 %0, t; }"
        : "=r"(sb) : "l"((void*)smem));

    const int tid  = threadIdx.x;
    const int lane = tid & 31;
    const int warp = tid >> 5;
    const int warpM = warp >> 2;   // 0..1 -> 64-row slab
    const int warpN = warp & 3;    // 0..3 -> 64-col slab
    const int bm = blockIdx.y * BM;
    const int bn = blockIdx.x * BN;

    const __half* Ag = g_Xh;  // [m][k]
    const __half* Bg = g_Mt;  // [n][k]

    float acc[4][8][4];
#pragma unroll
    for (int i = 0; i < 4; i++)
#pragma unroll
        for (int j = 0; j < 8; j++)
#pragma unroll
            for (int k = 0; k < 4; k++) acc[i][j][k] = 0.f;

    uint32_t zero = 0u;

    // Pre-swizzled base offsets; per-k-slice ks*32 applied via XOR.
    uint32_t aSw[4];
#pragma unroll
    for (int mi = 0; mi < 4; ++mi) {
        uint32_t off = (uint32_t)(warpM * 64 + mi * 16 + (lane & 15)) * 128
                     + (uint32_t)(lane >> 4) * 16;
        aSw[mi] = sw128(off);
    }
    uint32_t bSw[4];
#pragma unroll
    for (int p = 0; p < 4; ++p) {
        uint32_t row = (uint32_t)(warpN * 64 + p * 16 + ((lane & 16) >> 1) + (lane & 7));
        uint32_t off = row * 128 + (uint32_t)(lane & 8) * 2;
        bSw[p] = sw128(off);
    }

    auto load_stage = [&](int s, int kt) {
        const int kk = kt * BK;
        const uint32_t base = sb + (uint32_t)s * STAGE_BYTES;
#pragma unroll
        for (int i = 0; i < 12; ++i) {
            int cid = tid + i * 256;
            if (cid < 1024) {                       // A: 128 rows x 8 chunks
                int r = cid >> 3, c = cid & 7;
                cp_async16(base + sw128((uint32_t)(r * 128 + c * 16)),
                           Ag + (size_t)(bm + r) * NF + kk + c * 8);
            } else {                                // B: 256 rows x 8 chunks
                int cid2 = cid - 1024;
                int r = cid2 >> 3, c = cid2 & 7;
                cp_async16(base + A_BYTES + sw128((uint32_t)(r * 128 + c * 16)),
                           Bg + (size_t)(bn + r) * NF + kk + c * 8);
            }
        }
        cp_commit();
    };

    load_stage(0, 0);
    load_stage(1, 1);
    load_stage(2, 2);

    for (int kt = 0; kt < KT; ++kt) {
        asm volatile("cp.async.wait_group 2;\n" ::: "memory");
        __syncthreads();
        if (kt + 3 < KT) load_stage((kt + 3) & 3, kt + 3);
        else cp_commit();

        const uint32_t stA = sb + (uint32_t)(kt & 3) * STAGE_BYTES;
        const uint32_t stB = stA + A_BYTES;
#pragma unroll
        for (int ksp = 0; ksp < 2; ++ksp) {          // K=32 chunk: mma pair in f16
            const uint32_t kx0 = (uint32_t)(2 * ksp) << 5;
            const uint32_t kx1 = (uint32_t)(2 * ksp + 1) << 5;
            uint32_t af0[4][4], af1[4][4];
#pragma unroll
            for (int mi = 0; mi < 4; ++mi) {
                ldmatrix_x4(af0[mi], stA + (aSw[mi] ^ kx0));
                ldmatrix_x4(af1[mi], stA + (aSw[mi] ^ kx1));
            }
            uint32_t bf0[4][4], bf1[4][4];
#pragma unroll
            for (int p = 0; p < 4; ++p) {
                ldmatrix_x4(bf0[p], stB + (bSw[p] ^ kx0));
                ldmatrix_x4(bf1[p], stB + (bSw[p] ^ kx1));
            }
#pragma unroll
            for (int mi = 0; mi < 4; ++mi) {
#pragma unroll
                for (int ni = 0; ni < 8; ++ni) {
                    const int p = ni >> 1, h = (ni & 1) * 2;
                    uint32_t c2[2];
                    mma_h_z(c2, af0[mi], &bf0[p][h], zero);
                    mma_h(c2, af1[mi], &bf1[p][h]);
                    float2 f0 = __half22float2(*reinterpret_cast<__half2*>(&c2[0]));
                    float2 f1 = __half22float2(*reinterpret_cast<__half2*>(&c2[1]));
                    acc[mi][ni][0] += f0.x;
                    acc[mi][ni][1] += f0.y;
                    acc[mi][ni][2] += f1.x;
                    acc[mi][ni][3] += f1.y;
                }
            }
        }
    }

    // epilogue: relu(acc + bias), fp32 out
#pragma unroll
    for (int mi = 0; mi < 4; ++mi) {
#pragma unroll
        for (int ni = 0; ni < 8; ++ni) {
            int row = bm + warpM * 64 + mi * 16 + (lane >> 2);
            int col = bn + warpN * 64 + ni * 8 + (lane & 3) * 2;
            float b0 = __ldg(bias + col), b1 = __ldg(bias + col + 1);
            float2 v0, v1;
            v0.x = fmaxf(acc[mi][ni][0] + b0, 0.f);
            v0.y = fmaxf(acc[mi][ni][1] + b1, 0.f);
            v1.x = fmaxf(acc[mi][ni][2] + b0, 0.f);
            v1.y = fmaxf(acc[mi][ni][3] + b1, 0.f);
            *(float2*)(out + (size_t)row * NF + col) = v0;
            *(float2*)(out + (size_t)(row + 8) * NF + col) = v1;
        }
    }
}

// ---------------------------------------------------------------------------

extern "C" void kernel_launch(void* const* d_in, const int* in_sizes, int n_in,
                              void* d_out, int out_size) {
    const float* x  = (const float*)d_in[0];
    const float* c0 = (const float*)d_in[1];
    const float* c1 = (const float*)d_in[2];
    const float* c2 = (const float*)d_in[3];
    const float* c3 = (const float*)d_in[4];
    const float* bv = (const float*)d_in[5];
    float* out = (float*)d_out;

    static bool attr_done = false;
    if (!attr_done) {
        cudaFuncSetAttribute(k_gemm, cudaFuncAttributeMaxDynamicSharedMemorySize,
                             SMEM_TOTAL);
        attr_done = true;
    }

    k_prep0<<<16640, 256>>>(c0, c1, (const float4*)x);   // T2 + x->fp16
    k_build_T3<<<16384, 256>>>(c2);
    k_build_M<<<65536, 256>>>(c3);

    dim3 grid(NF / BN, NF / BM);  // (16, 32)
    k_gemm<<<grid, 256, SMEM_TOTAL>>>(bv, out);
    k_nop<<<1, 32>>>();
}

// round 10
// speedup vs baseline: 1.0588x; 1.0588x over previous
#include <cuda_runtime.h>
#include <cuda_fp16.h>
#include <cstdint>

// ---------------------------------------------------------------------------
// BayesKerasDense TT-dense: y = relu(x @ M + b)
// Stage 1: materialize TT-matrix M (fp16, transposed) + x -> fp16.
// Stage 2: mma.sync f16-accum GEMM (promote to fp32 every K=32).
//   R9 profile: f16-accum runs ~600 TF/s while busy (2x f32-accum), but
//   255 regs (spills) + 8 warps (occ 12.5%) left tensor at 42.9%.
//   R10: 512 threads / 16 warps, warp tile 32x64 -> 64 acc regs, ~105 live
//   regs, B frags loaded per 16-col group. Tensor-bound target ~250us.
// ---------------------------------------------------------------------------

#define NF 4096

__device__ float  g_T2[64 * 64 * 16];          // 256 KB
__device__ float  g_T3[512 * 512 * 16];        // 16.8 MB
__device__ __half g_Mt[(size_t)NF * NF];       // 32 MB, [n][k]
__device__ __half g_Xh[(size_t)NF * NF];       // 32 MB, [m][k]

// ---------------- stage 1: prep kernels ------------------------------------

// fused: blocks [0,256) build T2; blocks [256, 16640) convert x -> fp16
__global__ void k_prep0(const float* __restrict__ c0, const float* __restrict__ c1,
                        const float4* __restrict__ x4) {
    if (blockIdx.x < 256) {
        int idx = blockIdx.x * 256 + threadIdx.x;
        int r2 = idx & 15;
        int q2 = (idx >> 4) & 63;
        int p2 = idx >> 10;
        int a0 = p2 >> 3, a1 = p2 & 7;
        int b0 = q2 >> 3, b1 = q2 & 7;
        float s = 0.f;
#pragma unroll
        for (int r1 = 0; r1 < 16; ++r1)
            s += c0[(a0 * 8 + b0) * 16 + r1] * c1[((r1 * 8 + a1) * 8 + b1) * 16 + r2];
        g_T2[idx] = s;
    } else {
        int idx = (blockIdx.x - 256) * 256 + threadIdx.x;
        float4 v = x4[idx];
        __half2* o = (__half2*)g_Xh;
        o[idx * 2 + 0] = __floats2half2_rn(v.x, v.y);
        o[idx * 2 + 1] = __floats2half2_rn(v.z, v.w);
    }
}

__global__ void k_build_T3(const float* __restrict__ c2) {
    int idx = blockIdx.x * blockDim.x + threadIdx.x;
    if (idx >= 512 * 512 * 16) return;
    int r3 = idx & 15;
    int q3 = (idx >> 4) & 511;
    int p3 = idx >> 13;
    int p2 = p3 >> 3, a2 = p3 & 7;
    int q2 = q3 >> 3, b2 = q3 & 7;
    const float* t2 = &g_T2[((p2 << 6) + q2) << 4];
    float s = 0.f;
#pragma unroll
    for (int r2 = 0; r2 < 16; ++r2)
        s += t2[r2] * c2[((r2 * 8 + a2) * 8 + b2) * 16 + r3];
    g_T3[idx] = s;
}

__global__ void k_build_M(const float* __restrict__ c3) {
    int idx = blockIdx.x * blockDim.x + threadIdx.x;
    if (idx >= NF * NF) return;
    int a = idx & (NF - 1);
    int b = idx >> 12;
    int a3 = a & 7, p3 = a >> 3;
    int b3 = b & 7, q3 = b >> 3;
    const float* t3 = &g_T3[(((size_t)p3 << 9) + q3) << 4];
    float s = 0.f;
#pragma unroll
    for (int r3 = 0; r3 < 16; ++r3)
        s += t3[r3] * c3[(r3 * 8 + a3) * 8 + b3];
    g_Mt[(size_t)b * NF + a] = __float2half(s);
}

__global__ void k_nop() {}   // keeps ncu's capture slot aligned on k_gemm

// ---------------- stage 2: fp16 HMMA GEMM ----------------------------------

#define BM 128
#define BN 256
#define BK 64
#define KT (NF / BK)                 // 64
#define A_BYTES (BM * 128)           // 16 KB
#define B_BYTES (BN * 128)           // 32 KB
#define STAGE_BYTES (A_BYTES + B_BYTES)   // 48 KB
#define STAGES 4
#define SMEM_TOTAL (STAGES * STAGE_BYTES) // 192 KB
#define NTHR 512

__device__ __forceinline__ uint32_t sw128(uint32_t off) {
    return off ^ ((off >> 3) & 0x70);
}
__device__ __forceinline__ void cp_async16(uint32_t smem, const void* gmem) {
    asm volatile("cp.async.cg.shared.global [%0], [%1], 16;\n" :: "r"(smem), "l"(gmem));
}
__device__ __forceinline__ void cp_commit() {
    asm volatile("cp.async.commit_group;\n" ::: "memory");
}
__device__ __forceinline__ void ldmatrix_x4(uint32_t* r, uint32_t s) {
    asm volatile("ldmatrix.sync.aligned.m8n8.x4.shared.b16 {%0,%1,%2,%3}, [%4];\n"
                 : "=r"(r[0]), "=r"(r[1]), "=r"(r[2]), "=r"(r[3]) : "r"(s));
}
__device__ __forceinline__ void mma_h_z(uint32_t* d, const uint32_t* a,
                                        const uint32_t* b, uint32_t z) {
    asm volatile("mma.sync.aligned.m16n8k16.row.col.f16.f16.f16.f16 "
                 "{%0,%1}, {%2,%3,%4,%5}, {%6,%7}, {%8,%8};\n"
                 : "=r"(d[0]), "=r"(d[1])
                 : "r"(a[0]), "r"(a[1]), "r"(a[2]), "r"(a[3]),
                   "r"(b[0]), "r"(b[1]), "r"(z));
}
__device__ __forceinline__ void mma_h(uint32_t* d, const uint32_t* a,
                                      const uint32_t* b) {
    asm volatile("mma.sync.aligned.m16n8k16.row.col.f16.f16.f16.f16 "
                 "{%0,%1}, {%2,%3,%4,%5}, {%6,%7}, {%0,%1};\n"
                 : "+r"(d[0]), "+r"(d[1])
                 : "r"(a[0]), "r"(a[1]), "r"(a[2]), "r"(a[3]),
                   "r"(b[0]), "r"(b[1]));
}

__global__ __launch_bounds__(NTHR, 1) void k_gemm(const float* __restrict__ bias,
                                                  float* __restrict__ out) {
    extern __shared__ char smem[];
    uint32_t sb;
    asm("{ .reg .u64 t; cvta.to.shared.u64 t, %1; cvt.u32.u64 %0, t; }"
        : "=r"(sb) : "l"((void*)smem));

    const int tid  = threadIdx.x;
    const int lane = tid & 31;
    const int warp = tid >> 5;      // 0..15
    const int warpM = warp & 3;     // 4 slabs of 32 rows
    const int warpN = warp >> 2;    // 4 slabs of 64 cols
    const int bm = blockIdx.y * BM;
    const int bn = blockIdx.x * BN;

    const __half* Ag = g_Xh;  // [m][k]
    const __half* Bg = g_Mt;  // [n][k]

    // warp tile 32x64: mi 0..1 (16-row), ni 0..7 (8-col)
    float acc[2][8][4];
#pragma unroll
    for (int i = 0; i < 2; i++)
#pragma unroll
        for (int j = 0; j < 8; j++)
#pragma unroll
            for (int k = 0; k < 4; k++) acc[i][j][k] = 0.f;

    uint32_t zero = 0u;

    // Pre-swizzled bases (bits 5-6 clear pre-swizzle); k-slice offset via XOR.
    uint32_t aSw[2];
#pragma unroll
    for (int mi = 0; mi < 2; ++mi) {
        uint32_t off = (uint32_t)(warpM * 32 + mi * 16 + (lane & 15)) * 128
                     + (uint32_t)(lane >> 4) * 16;
        aSw[mi] = sw128(off);
    }
    uint32_t bSw[4];
#pragma unroll
    for (int p = 0; p < 4; ++p) {
        uint32_t row = (uint32_t)(warpN * 64 + p * 16 + ((lane & 16) >> 1) + (lane & 7));
        uint32_t off = row * 128 + (uint32_t)(lane & 8) * 2;
        bSw[p] = sw128(off);
    }

    // stage loader: 3072 x 16B chunks (1024 A + 2048 B), 6 per thread
    auto load_stage = [&](int s, int kt) {
        const int kk = kt * BK;
        const uint32_t base = sb + (uint32_t)s * STAGE_BYTES;
#pragma unroll
        for (int i = 0; i < 6; ++i) {
            int cid = tid + i * NTHR;
            if (cid < 1024) {                       // A: 128 rows x 8 chunks
                int r = cid >> 3, c = cid & 7;
                cp_async16(base + sw128((uint32_t)(r * 128 + c * 16)),
                           Ag + (size_t)(bm + r) * NF + kk + c * 8);
            } else {                                // B: 256 rows x 8 chunks
                int cid2 = cid - 1024;
                int r = cid2 >> 3, c = cid2 & 7;
                cp_async16(base + A_BYTES + sw128((uint32_t)(r * 128 + c * 16)),
                           Bg + (size_t)(bn + r) * NF + kk + c * 8);
            }
        }
        cp_commit();
    };

    load_stage(0, 0);
    load_stage(1, 1);
    load_stage(2, 2);

    for (int kt = 0; kt < KT; ++kt) {
        asm volatile("cp.async.wait_group 2;\n" ::: "memory");
        __syncthreads();
        if (kt + 3 < KT) load_stage((kt + 3) & 3, kt + 3);
        else cp_commit();

        const uint32_t stA = sb + (uint32_t)(kt & 3) * STAGE_BYTES;
        const uint32_t stB = stA + A_BYTES;
#pragma unroll
        for (int ksp = 0; ksp < 2; ++ksp) {          // K=32 chunk in f16
            const uint32_t kx0 = (uint32_t)(2 * ksp) << 5;
            const uint32_t kx1 = (uint32_t)(2 * ksp + 1) << 5;
            uint32_t af0[2][4], af1[2][4];
#pragma unroll
            for (int mi = 0; mi < 2; ++mi) {
                ldmatrix_x4(af0[mi], stA + (aSw[mi] ^ kx0));
                ldmatrix_x4(af1[mi], stA + (aSw[mi] ^ kx1));
            }
#pragma unroll
            for (int p = 0; p < 4; ++p) {            // 16-col B group
                uint32_t bf0[4], bf1[4];
                ldmatrix_x4(bf0, stB + (bSw[p] ^ kx0));
                ldmatrix_x4(bf1, stB + (bSw[p] ^ kx1));
#pragma unroll
                for (int mi = 0; mi < 2; ++mi) {
#pragma unroll
                    for (int h = 0; h < 2; ++h) {    // two n8 frags in group
                        uint32_t c2[2];
                        mma_h_z(c2, af0[mi], &bf0[h * 2], zero);
                        mma_h(c2, af1[mi], &bf1[h * 2]);
                        const int ni = p * 2 + h;
                        float2 f0 = __half22float2(*reinterpret_cast<__half2*>(&c2[0]));
                        float2 f1 = __half22float2(*reinterpret_cast<__half2*>(&c2[1]));
                        acc[mi][ni][0] += f0.x;
                        acc[mi][ni][1] += f0.y;
                        acc[mi][ni][2] += f1.x;
                        acc[mi][ni][3] += f1.y;
                    }
                }
            }
        }
    }

    // epilogue: relu(acc + bias), fp32 out
#pragma unroll
    for (int mi = 0; mi < 2; ++mi) {
#pragma unroll
        for (int ni = 0; ni < 8; ++ni) {
            int row = bm + warpM * 32 + mi * 16 + (lane >> 2);
            int col = bn + warpN * 64 + ni * 8 + (lane & 3) * 2;
            float b0 = __ldg(bias + col), b1 = __ldg(bias + col + 1);
            float2 v0, v1;
            v0.x = fmaxf(acc[mi][ni][0] + b0, 0.f);
            v0.y = fmaxf(acc[mi][ni][1] + b1, 0.f);
            v1.x = fmaxf(acc[mi][ni][2] + b0, 0.f);
            v1.y = fmaxf(acc[mi][ni][3] + b1, 0.f);
            *(float2*)(out + (size_t)row * NF + col) = v0;
            *(float2*)(out + (size_t)(row + 8) * NF + col) = v1;
        }
    }
}

// ---------------------------------------------------------------------------

extern "C" void kernel_launch(void* const* d_in, const int* in_sizes, int n_in,
                              void* d_out, int out_size) {
    const float* x  = (const float*)d_in[0];
    const float* c0 = (const float*)d_in[1];
    const float* c1 = (const float*)d_in[2];
    const float* c2 = (const float*)d_in[3];
    const float* c3 = (const float*)d_in[4];
    const float* bv = (const float*)d_in[5];
    float* out = (float*)d_out;

    static bool attr_done = false;
    if (!attr_done) {
        cudaFuncSetAttribute(k_gemm, cudaFuncAttributeMaxDynamicSharedMemorySize,
                             SMEM_TOTAL);
        attr_done = true;
    }

    k_prep0<<<16640, 256>>>(c0, c1, (const float4*)x);   // T2 + x->fp16
    k_build_T3<<<16384, 256>>>(c2);
    k_build_M<<<65536, 256>>>(c3);

    dim3 grid(NF / BN, NF / BM);  // (16, 32)
    k_gemm<<<grid, NTHR, SMEM_TOTAL>>>(bv, out);
    k_nop<<<1, 32>>>();
}